// round 11
// baseline (speedup 1.0000x reference)
#include <cuda_runtime.h>

#define HW   9216
#define BB   4
#define CC   64
#define DGRP 8
#define CPG  8
#define OFFC 216

typedef unsigned long long ull;

// ---------------- scratch (__device__ globals; no allocation allowed) ----------------
__device__ __align__(16) float g_om  [BB * OFFC * HW];       // offset-conv output (oy|ox|m)
__device__ __align__(16) float g_xt  [BB * DGRP * HW * CPG]; // x transposed: (b,g,h,w,c)
__device__ __align__(16) float g_fea [BB * CC * HW];         // leaky(dcn) output
__device__ __align__(16) float g_wofft[576 * OFFC];          // w_off  -> [(ci*9+tap)][oc]
__device__ __align__(16) float g_wdt [576 * CC];             // w_dcn  -> [(ci*9+tap)][oc]
__device__ __align__(16) float g_wct [576 * CC];             // w_conv1-> [(ci*9+tap)][oc]

// ---------------- f32x2 helpers (Blackwell packed fp32, 2x FFMA rate) ----------------
__device__ __forceinline__ void fma2(ull &d, ull a, ull b) {
    asm("fma.rn.f32x2 %0, %1, %2, %0;" : "+l"(d) : "l"(a), "l"(b));
}
__device__ __forceinline__ ull pk2(float lo, float hi) {
    ull r; asm("mov.b64 %0, {%1,%2};" : "=l"(r) : "f"(lo), "f"(hi)); return r;
}
__device__ __forceinline__ float2 upk(ull v) {
    float2 r; asm("mov.b64 {%0,%1}, %2;" : "=f"(r.x), "=f"(r.y) : "l"(v)); return r;
}

// ---------------- K0a: weight transpose [OC][CI][3][3] -> [(ci*9+tap)][OC] ----------------
__global__ void k_wt(const float* __restrict__ src, int which, int OC) {
    int e = blockIdx.x * 256 + threadIdx.x;
    int total = OC * 64 * 9;
    if (e >= total) return;
    float* dst = (which == 0) ? g_wofft : ((which == 1) ? g_wdt : g_wct);
    int oc = e % OC;
    int rt = e / OC;          // ci*9 + tap
    int ci = rt / 9, tap = rt % 9;
    dst[e] = src[(oc * 64 + ci) * 9 + tap];
}

// ---------------- K0b: x transpose (b,c,h,w) -> (b,g,h,w,cpg) ----------------
__global__ void k_xt(const float* __restrict__ x) {
    int bgh = blockIdx.x;             // b*DGRP*96 + g*96 + h
    int h = bgh % 96; int bg = bgh / 96;
    int g = bg % DGRP; int b = bg / DGRP;
    int w = threadIdx.x;
    const float* xp = x + (size_t)(b * CC + g * CPG) * HW + h * 96 + w;
    float v[8];
#pragma unroll
    for (int c = 0; c < 8; c++) v[c] = xp[c * HW];
    float4* d4 = (float4*)(g_xt + ((size_t)(b * DGRP + g) * HW + h * 96 + w) * CPG);
    d4[0] = make_float4(v[0], v[1], v[2], v[3]);
    d4[1] = make_float4(v[4], v[5], v[6], v[7]);
}

// ---------------- K1/K3: 3x3 conv (pad 1), GEMM-tiled, f32x2 ----------------
// Tile: 64 out-channels x (4 rows x 32 cols). Thread: 4 oc x 8 pos.
// Input staged DUPLICATED in smem ((v,v) per 64-bit slot) so the broadcast
// operand of fma.rn.f32x2 comes straight from LDS.64 with zero packing MOVs.
template<bool IS_OFF>
__global__ __launch_bounds__(256, 2) void k_conv(const float* __restrict__ a,
                                                 const float* __restrict__ bias,
                                                 float* __restrict__ outp) {
    const int OCTOT = IS_OFF ? OFFC : 64;
    __shared__ __align__(16) ull   in_s2[8 * 6 * 36];     // duplicated input: 13.8 KB
    __shared__ __align__(16) float w_s  [8 * 9 * 64];     // weights: 18 KB
    int tid = threadIdx.x;
    int tx = tid & 15, tp = tid >> 4;
    int r = tp >> 2, xq = (tp & 3) << 3;
    int x0 = blockIdx.x << 5, y0 = blockIdx.y << 2;
    int b, OC0;
    if (IS_OFF) { b = blockIdx.z >> 2; OC0 = (blockIdx.z & 3) << 6; }
    else        { b = blockIdx.z;      OC0 = 0; }
    int oc0 = OC0 + (tx << 2);

    const float* wt = IS_OFF ? g_wofft : g_wct;
    const float* ib = (IS_OFF ? a : g_fea) + (size_t)b * CC * HW;

    float bb[4];
#pragma unroll
    for (int q = 0; q < 4; q++) bb[q] = (oc0 + q < OCTOT) ? bias[oc0 + q] : 0.f;
    ull acc0[8], acc1[8];
#pragma unroll
    for (int j = 0; j < 8; j++) { acc0[j] = pk2(bb[0], bb[1]); acc1[j] = pk2(bb[2], bb[3]); }

    for (int ci0 = 0; ci0 < 64; ci0 += 8) {
        // stage input tile (6 rows x 34 cols halo, 8 ci), duplicated, zero-padded borders
        for (int e = tid; e < 1728; e += 256) {
            int ci = e / 216, rem = e % 216;
            int row = rem / 36, col = rem % 36;
            int gy = y0 - 1 + row, gx = x0 - 1 + col;
            float v = 0.f;
            if (col < 34 && gy >= 0 && gy < 96 && gx >= 0 && gx < 96)
                v = ib[(ci0 + ci) * HW + gy * 96 + gx];
            *(float2*)&in_s2[e] = make_float2(v, v);
        }
        // stage weights [ci][tap][64 oc]
        for (int e = tid; e < 4608; e += 256) {
            int oc = e & 63; int rt = e >> 6;
            int ci = rt / 9, tap = rt % 9;
            float v = 0.f;
            if (OC0 + oc < OCTOT)
                v = wt[((ci0 + ci) * 9 + tap) * OCTOT + OC0 + oc];
            w_s[e] = v;
        }
        __syncthreads();
        const ulonglong2* w16 = (const ulonglong2*)w_s;
#pragma unroll
        for (int ci = 0; ci < 8; ci++) {
#pragma unroll
            for (int ky = 0; ky < 3; ky++) {
                int base = ci * 216 + (r + ky) * 36 + xq;
                ull rd[11];
#pragma unroll
                for (int i = 0; i < 11; i++) rd[i] = in_s2[base + i];
#pragma unroll
                for (int kx = 0; kx < 3; kx++) {
                    ulonglong2 wq = w16[(ci * 9 + ky * 3 + kx) * 16 + tx];
#pragma unroll
                    for (int j = 0; j < 8; j++) {
                        fma2(acc0[j], wq.x, rd[kx + j]);
                        fma2(acc1[j], wq.y, rd[kx + j]);
                    }
                }
            }
        }
        __syncthreads();
    }

    // epilogue
    float va[4][8];
#pragma unroll
    for (int j = 0; j < 8; j++) {
        float2 u0 = upk(acc0[j]), u1 = upk(acc1[j]);
        va[0][j] = u0.x; va[1][j] = u0.y; va[2][j] = u1.x; va[3][j] = u1.y;
    }
    int y = y0 + r, xb = x0 + xq;
    if (IS_OFF) {
#pragma unroll
        for (int q = 0; q < 4; q++) {
            int oc = oc0 + q;
            if (oc < OFFC) {
                float4* dst = (float4*)(g_om + ((size_t)b * OFFC + oc) * HW + y * 96 + xb);
                dst[0] = make_float4(va[q][0], va[q][1], va[q][2], va[q][3]);
                dst[1] = make_float4(va[q][4], va[q][5], va[q][6], va[q][7]);
            }
        }
    } else {
#pragma unroll
        for (int q = 0; q < 4; q++) {
            int oc = oc0 + q;
            size_t off = ((size_t)b * CC + oc) * HW + y * 96 + xb;
            const float4* res = (const float4*)(a + off);
            float4 r0 = res[0], r1 = res[1];
            float4* dst = (float4*)(outp + off);
            dst[0] = make_float4(va[q][0] + r0.x, va[q][1] + r0.y, va[q][2] + r0.z, va[q][3] + r0.w);
            dst[1] = make_float4(va[q][4] + r1.x, va[q][5] + r1.y, va[q][6] + r1.z, va[q][7] + r1.w);
        }
    }
}

// ---------------- K2: deform bilinear sample + DCN einsum + leaky ----------------
// Sampled values staged DUPLICATED in smem; weights read as ulonglong2 pairs.
#define AXPY4(s, wc, t) { (s).x += (wc)*(t).x; (s).y += (wc)*(t).y; (s).z += (wc)*(t).z; (s).w += (wc)*(t).w; }

__global__ __launch_bounds__(256, 2) void k_dcn(const float* __restrict__ bias) {
    __shared__ __align__(16) ull   val_s2[8 * 128];   // duplicated sampled vals: 8 KB
    __shared__ __align__(16) float w_s   [8 * 64];
    int tid = threadIdx.x;
    int tx = tid & 15, tp = tid >> 4;
    int rG = tp >> 2, xqG = (tp & 3) << 3;
    int x0 = blockIdx.x << 5, y0 = blockIdx.y << 2;
    int b = blockIdx.z;
    int oc0 = tx << 2;

    // staging mapping: 2 thread-halves x 128 positions, each half does 4 channels
    int p = tid & 127, chalf = tid >> 7;
    int pr = p >> 5, px = p & 31;
    int yy = y0 + pr, xx = x0 + px;
    int posi = yy * 96 + xx;

    ull acc0[8], acc1[8];
    {
        float b0 = bias[oc0], b1 = bias[oc0 + 1], b2 = bias[oc0 + 2], b3 = bias[oc0 + 3];
#pragma unroll
        for (int j = 0; j < 8; j++) { acc0[j] = pk2(b0, b1); acc1[j] = pk2(b2, b3); }
    }

    const float* omb = g_om + (size_t)b * OFFC * HW;
    for (int g = 0; g < 8; g++) {
        const float4* xg4 = (const float4*)(g_xt + (size_t)(b * DGRP + g) * HW * CPG);
#pragma unroll 1
        for (int ky = 0; ky < 3; ky++) {
#pragma unroll 1
            for (int kx = 0; kx < 3; kx++) {
                int k = ky * 3 + kx;
                int gk = g * 9 + k;
                float oy = omb[gk * HW + posi];
                float ox = omb[(72 + gk) * HW + posi];
                float mv = omb[(144 + gk) * HW + posi];
                float mask = 1.f / (1.f + __expf(-mv));
                float py = (float)(yy + ky - 1) + oy;
                float pxx = (float)(xx + kx - 1) + ox;
                float fy0 = floorf(py), fx0 = floorf(pxx);
                int yi = (int)fy0, xi = (int)fx0;
                float fy = py - fy0, fx = pxx - fx0;
                float w00 = (1.f - fy) * (1.f - fx), w01w = (1.f - fy) * fx;
                float w10 = fy * (1.f - fx), w11 = fy * fx;
                bool vy0 = (yi >= 0) && (yi < 96);
                bool vy1 = (yi >= -1) && (yi < 95);
                bool vx0 = (xi >= 0) && (xi < 96);
                bool vx1 = (xi >= -1) && (xi < 95);
                float4 s = make_float4(0.f, 0.f, 0.f, 0.f);
                if (vy0) {
                    int yb = yi * 96;
                    if (vx0) { float4 t = xg4[(yb + xi) * 2 + chalf];     AXPY4(s, w00, t); }
                    if (vx1) { float4 t = xg4[(yb + xi + 1) * 2 + chalf]; AXPY4(s, w01w, t); }
                }
                if (vy1) {
                    int yb = (yi + 1) * 96;
                    if (vx0) { float4 t = xg4[(yb + xi) * 2 + chalf];     AXPY4(s, w10, t); }
                    if (vx1) { float4 t = xg4[(yb + xi + 1) * 2 + chalf]; AXPY4(s, w11, t); }
                }
                int c0 = chalf << 2;
                float sv0 = s.x * mask, sv1 = s.y * mask, sv2 = s.z * mask, sv3 = s.w * mask;
                *(float2*)&val_s2[(c0 + 0) * 128 + p] = make_float2(sv0, sv0);
                *(float2*)&val_s2[(c0 + 1) * 128 + p] = make_float2(sv1, sv1);
                *(float2*)&val_s2[(c0 + 2) * 128 + p] = make_float2(sv2, sv2);
                *(float2*)&val_s2[(c0 + 3) * 128 + p] = make_float2(sv3, sv3);
                if (tid < 128) {
                    int c = tid >> 4, o4 = tid & 15;
                    ((float4*)w_s)[c * 16 + o4] =
                        ((const float4*)g_wdt)[((g * 8 + c) * 9 + k) * 16 + o4];
                }
                __syncthreads();
                const ulonglong2* w16 = (const ulonglong2*)w_s;
#pragma unroll
                for (int c = 0; c < 8; c++) {
                    int vb = c * 128 + rG * 32 + xqG;
                    ull rd[8];
#pragma unroll
                    for (int j = 0; j < 8; j++) rd[j] = val_s2[vb + j];
                    ulonglong2 wq = w16[c * 16 + tx];
#pragma unroll
                    for (int j = 0; j < 8; j++) {
                        fma2(acc0[j], wq.x, rd[j]);
                        fma2(acc1[j], wq.y, rd[j]);
                    }
                }
                __syncthreads();
            }
        }
    }

    // epilogue: leaky relu, store fea
    float va[4][8];
#pragma unroll
    for (int j = 0; j < 8; j++) {
        float2 u0 = upk(acc0[j]), u1 = upk(acc1[j]);
        va[0][j] = (u0.x >= 0.f) ? u0.x : 0.2f * u0.x;
        va[1][j] = (u0.y >= 0.f) ? u0.y : 0.2f * u0.y;
        va[2][j] = (u1.x >= 0.f) ? u1.x : 0.2f * u1.x;
        va[3][j] = (u1.y >= 0.f) ? u1.y : 0.2f * u1.y;
    }
    int y = y0 + rG, xb = x0 + xqG;
#pragma unroll
    for (int q = 0; q < 4; q++) {
        int oc = oc0 + q;
        float4* dst = (float4*)(g_fea + ((size_t)b * CC + oc) * HW + y * 96 + xb);
        dst[0] = make_float4(va[q][0], va[q][1], va[q][2], va[q][3]);
        dst[1] = make_float4(va[q][4], va[q][5], va[q][6], va[q][7]);
    }
}

// ---------------- launch ----------------
extern "C" void kernel_launch(void* const* d_in, const int* in_sizes, int n_in,
                              void* d_out, int out_size) {
    const float* x       = (const float*)d_in[0];
    const float* offset  = (const float*)d_in[1];
    const float* w_off   = (const float*)d_in[2];
    const float* b_off   = (const float*)d_in[3];
    const float* w_dcn   = (const float*)d_in[4];
    const float* b_dcn   = (const float*)d_in[5];
    const float* w_conv1 = (const float*)d_in[6];
    const float* b_conv1 = (const float*)d_in[7];
    float* out = (float*)d_out;
    (void)in_sizes; (void)n_in; (void)out_size;

    k_wt<<<486, 256>>>(w_off, 0, OFFC);     // -> g_wofft
    k_wt<<<144, 256>>>(w_dcn, 1, 64);       // -> g_wdt
    k_wt<<<144, 256>>>(w_conv1, 2, 64);     // -> g_wct
    k_xt<<<3072, 96>>>(x);                  // -> g_xt

    k_conv<true><<<dim3(3, 24, 16), 256>>>(offset, b_off, nullptr);  // -> g_om
    k_dcn<<<dim3(3, 24, 4), 256>>>(b_dcn);                           // -> g_fea
    k_conv<false><<<dim3(3, 24, 4), 256>>>(x, b_conv1, out);         // -> out
}

// round 12
// speedup vs baseline: 1.2591x; 1.2591x over previous
#include <cuda_runtime.h>

#define HW   9216
#define BB   4
#define CC   64
#define DGRP 8
#define CPG  8
#define OFFC 216

typedef unsigned long long ull;

// ---------------- scratch (__device__ globals; no allocation allowed) ----------------
__device__ __align__(16) float g_om  [BB * OFFC * HW];       // offset-conv output (oy|ox|m)
__device__ __align__(16) float g_xt  [BB * DGRP * HW * CPG]; // x transposed: (b,g,h,w,c)
__device__ __align__(16) float g_fea [BB * CC * HW];         // leaky(dcn) output
__device__ __align__(16) float g_wofft[576 * OFFC];          // w_off  -> [(ci*9+tap)][oc]
__device__ __align__(16) float g_wdt [576 * CC];             // w_dcn  -> [(ci*9+tap)][oc]
__device__ __align__(16) float g_wct [576 * CC];             // w_conv1-> [(ci*9+tap)][oc]

// ---------------- f32x2 helpers (Blackwell packed fp32, 2x FFMA rate) ----------------
__device__ __forceinline__ void fma2(ull &d, ull a, ull b) {
    asm("fma.rn.f32x2 %0, %1, %2, %0;" : "+l"(d) : "l"(a), "l"(b));
}
__device__ __forceinline__ ull pk2(float lo, float hi) {
    ull r; asm("mov.b64 %0, {%1,%2};" : "=l"(r) : "f"(lo), "f"(hi)); return r;
}
__device__ __forceinline__ float2 upk(ull v) {
    float2 r; asm("mov.b64 {%0,%1}, %2;" : "=f"(r.x), "=f"(r.y) : "l"(v)); return r;
}

// ---------------- K0a: weight transpose [OC][CI][3][3] -> [(ci*9+tap)][OC] ----------------
__global__ void k_wt(const float* __restrict__ src, int which, int OC) {
    int e = blockIdx.x * 256 + threadIdx.x;
    int total = OC * 64 * 9;
    if (e >= total) return;
    float* dst = (which == 0) ? g_wofft : ((which == 1) ? g_wdt : g_wct);
    int oc = e % OC;
    int rt = e / OC;          // ci*9 + tap
    int ci = rt / 9, tap = rt % 9;
    dst[e] = src[(oc * 64 + ci) * 9 + tap];
}

// ---------------- K0b: x transpose (b,c,h,w) -> (b,g,h,w,cpg) ----------------
__global__ void k_xt(const float* __restrict__ x) {
    int bgh = blockIdx.x;             // b*DGRP*96 + g*96 + h
    int h = bgh % 96; int bg = bgh / 96;
    int g = bg % DGRP; int b = bg / DGRP;
    int w = threadIdx.x;
    const float* xp = x + (size_t)(b * CC + g * CPG) * HW + h * 96 + w;
    float v[8];
#pragma unroll
    for (int c = 0; c < 8; c++) v[c] = xp[c * HW];
    float4* d4 = (float4*)(g_xt + ((size_t)(b * DGRP + g) * HW + h * 96 + w) * CPG);
    d4[0] = make_float4(v[0], v[1], v[2], v[3]);
    d4[1] = make_float4(v[4], v[5], v[6], v[7]);
}

// ---------------- K1/K3: 3x3 conv (pad 1), GEMM-tiled, f32x2 ----------------
// Block tile: 64 oc x (8 rows x 32 cols). Thread: 8 oc x 8 pos (32 ull accs).
// Fat oc-tile cuts smem bytes/FFMA2 from 2.0 -> 1.5 (crossbar 96 B/cyc < 128),
// leaving the fma pipe as the sole binding resource. MOV packing hidden in
// the 96 spare issue slots per 96-FFMA2 (192-cycle) inner iteration.
template<bool IS_OFF>
__global__ __launch_bounds__(256, 2) void k_conv(const float* __restrict__ a,
                                                 const float* __restrict__ bias,
                                                 float* __restrict__ outp) {
    const int OCTOT = IS_OFF ? OFFC : 64;
    __shared__ __align__(16) float in_s[8 * 10 * 36];   // 11.5 KB (halo 10x34, pitch 36)
    __shared__ __align__(16) float w_s [8 * 9 * 64];    // 18 KB
    int tid = threadIdx.x;
    int tx = tid & 7, tp = tid >> 3;          // tx: oc-group (8 oc), tp: 0..31 pos-group
    int r = tp >> 2, xq = (tp & 3) << 3;      // r: 0..7 row, xq: {0,8,16,24}
    int x0 = blockIdx.x << 5, y0 = blockIdx.y << 3;
    int b, OC0;
    if (IS_OFF) { b = blockIdx.z >> 2; OC0 = (blockIdx.z & 3) << 6; }
    else        { b = blockIdx.z;      OC0 = 0; }
    int oc0 = OC0 + (tx << 3);                // 8 output channels per thread

    const float* wt = IS_OFF ? g_wofft : g_wct;
    const float* ib = (IS_OFF ? a : g_fea) + (size_t)b * CC * HW;

    ull acc[4][8];                            // 4 oc-pairs x 8 pos
#pragma unroll
    for (int q = 0; q < 4; q++) {
        float b0 = (oc0 + 2 * q     < OCTOT) ? bias[oc0 + 2 * q]     : 0.f;
        float b1 = (oc0 + 2 * q + 1 < OCTOT) ? bias[oc0 + 2 * q + 1] : 0.f;
#pragma unroll
        for (int j = 0; j < 8; j++) acc[q][j] = pk2(b0, b1);
    }

    for (int ci0 = 0; ci0 < 64; ci0 += 8) {
        // stage input tile (10 rows x 34 cols halo, 8 ci), zero-padded borders
        for (int e = tid; e < 2880; e += 256) {
            int ci = e / 360, rem = e % 360;
            int row = rem / 36, col = rem % 36;
            int gy = y0 - 1 + row, gx = x0 - 1 + col;
            float v = 0.f;
            if (col < 34 && gy >= 0 && gy < 96 && gx >= 0 && gx < 96)
                v = ib[(ci0 + ci) * HW + gy * 96 + gx];
            in_s[e] = v;
        }
        // stage weights [ci][tap][64 oc]
        for (int e = tid; e < 4608; e += 256) {
            int oc = e & 63; int rt = e >> 6;
            int ci = rt / 9, tap = rt % 9;
            float v = 0.f;
            if (OC0 + oc < OCTOT)
                v = wt[((ci0 + ci) * 9 + tap) * OCTOT + OC0 + oc];
            w_s[e] = v;
        }
        __syncthreads();
        const float4* in4 = (const float4*)in_s;
        const float4* w4p = (const float4*)w_s;
#pragma unroll
        for (int ci = 0; ci < 8; ci++) {
#pragma unroll
            for (int ky = 0; ky < 3; ky++) {
                int base4 = (ci * 360 + (r + ky) * 36 + xq) >> 2;
                float4 a0 = in4[base4], a1 = in4[base4 + 1], a2 = in4[base4 + 2];
                float rr[12] = {a0.x, a0.y, a0.z, a0.w, a1.x, a1.y, a1.z, a1.w,
                                a2.x, a2.y, a2.z, a2.w};
                ull rd[12];
#pragma unroll
                for (int i = 0; i < 12; i++) rd[i] = pk2(rr[i], rr[i]);
#pragma unroll
                for (int kx = 0; kx < 3; kx++) {
                    int wb4 = (ci * 9 + ky * 3 + kx) * 16 + (tx << 1);
                    float4 w0 = w4p[wb4], w1 = w4p[wb4 + 1];
                    ull wq0 = pk2(w0.x, w0.y), wq1 = pk2(w0.z, w0.w);
                    ull wq2 = pk2(w1.x, w1.y), wq3 = pk2(w1.z, w1.w);
#pragma unroll
                    for (int j = 0; j < 8; j++) {
                        fma2(acc[0][j], wq0, rd[kx + j]);
                        fma2(acc[1][j], wq1, rd[kx + j]);
                        fma2(acc[2][j], wq2, rd[kx + j]);
                        fma2(acc[3][j], wq3, rd[kx + j]);
                    }
                }
            }
        }
        __syncthreads();
    }

    // epilogue: unpack 8 oc x 8 pos
    float va[8][8];
#pragma unroll
    for (int q = 0; q < 4; q++)
#pragma unroll
        for (int j = 0; j < 8; j++) {
            float2 u = upk(acc[q][j]);
            va[2 * q][j] = u.x; va[2 * q + 1][j] = u.y;
        }
    int y = y0 + r, xb = x0 + xq;
    if (IS_OFF) {
#pragma unroll
        for (int o = 0; o < 8; o++) {
            int oc = oc0 + o;
            if (oc < OFFC) {
                float4* dst = (float4*)(g_om + ((size_t)b * OFFC + oc) * HW + y * 96 + xb);
                dst[0] = make_float4(va[o][0], va[o][1], va[o][2], va[o][3]);
                dst[1] = make_float4(va[o][4], va[o][5], va[o][6], va[o][7]);
            }
        }
    } else {
#pragma unroll
        for (int o = 0; o < 8; o++) {
            int oc = oc0 + o;
            size_t off = ((size_t)b * CC + oc) * HW + y * 96 + xb;
            const float4* res = (const float4*)(a + off);
            float4 r0 = res[0], r1 = res[1];
            float4* dst = (float4*)(outp + off);
            dst[0] = make_float4(va[o][0] + r0.x, va[o][1] + r0.y, va[o][2] + r0.z, va[o][3] + r0.w);
            dst[1] = make_float4(va[o][4] + r1.x, va[o][5] + r1.y, va[o][6] + r1.z, va[o][7] + r1.w);
        }
    }
}

// ---------------- K2: deform bilinear sample + DCN einsum + leaky ----------------
// (reverted to the measured-487us form: float smem + register pk2 packing)
#define AXPY4(s, wc, t) { (s).x += (wc)*(t).x; (s).y += (wc)*(t).y; (s).z += (wc)*(t).z; (s).w += (wc)*(t).w; }

__global__ __launch_bounds__(256, 2) void k_dcn(const float* __restrict__ bias) {
    __shared__ __align__(16) float val_s[8 * 128];
    __shared__ __align__(16) float w_s[8 * 64];
    int tid = threadIdx.x;
    int tx = tid & 15, tp = tid >> 4;
    int rG = tp >> 2, xqG = (tp & 3) << 3;
    int x0 = blockIdx.x << 5, y0 = blockIdx.y << 2;
    int b = blockIdx.z;
    int oc0 = tx << 2;

    int p = tid & 127, chalf = tid >> 7;
    int pr = p >> 5, px = p & 31;
    int yy = y0 + pr, xx = x0 + px;
    int posi = yy * 96 + xx;

    ull acc0[8], acc1[8];
    {
        float b0 = bias[oc0], b1 = bias[oc0 + 1], b2 = bias[oc0 + 2], b3 = bias[oc0 + 3];
#pragma unroll
        for (int j = 0; j < 8; j++) { acc0[j] = pk2(b0, b1); acc1[j] = pk2(b2, b3); }
    }

    const float* omb = g_om + (size_t)b * OFFC * HW;
    for (int g = 0; g < 8; g++) {
        const float4* xg4 = (const float4*)(g_xt + (size_t)(b * DGRP + g) * HW * CPG);
#pragma unroll 1
        for (int ky = 0; ky < 3; ky++) {
#pragma unroll 1
            for (int kx = 0; kx < 3; kx++) {
                int k = ky * 3 + kx;
                int gk = g * 9 + k;
                float oy = omb[gk * HW + posi];
                float ox = omb[(72 + gk) * HW + posi];
                float mv = omb[(144 + gk) * HW + posi];
                float mask = 1.f / (1.f + __expf(-mv));
                float py = (float)(yy + ky - 1) + oy;
                float pxx = (float)(xx + kx - 1) + ox;
                float fy0 = floorf(py), fx0 = floorf(pxx);
                int yi = (int)fy0, xi = (int)fx0;
                float fy = py - fy0, fx = pxx - fx0;
                float w00 = (1.f - fy) * (1.f - fx), w01w = (1.f - fy) * fx;
                float w10 = fy * (1.f - fx), w11 = fy * fx;
                bool vy0 = (yi >= 0) && (yi < 96);
                bool vy1 = (yi >= -1) && (yi < 95);
                bool vx0 = (xi >= 0) && (xi < 96);
                bool vx1 = (xi >= -1) && (xi < 95);
                float4 s = make_float4(0.f, 0.f, 0.f, 0.f);
                if (vy0) {
                    int yb = yi * 96;
                    if (vx0) { float4 t = xg4[(yb + xi) * 2 + chalf];     AXPY4(s, w00, t); }
                    if (vx1) { float4 t = xg4[(yb + xi + 1) * 2 + chalf]; AXPY4(s, w01w, t); }
                }
                if (vy1) {
                    int yb = (yi + 1) * 96;
                    if (vx0) { float4 t = xg4[(yb + xi) * 2 + chalf];     AXPY4(s, w10, t); }
                    if (vx1) { float4 t = xg4[(yb + xi + 1) * 2 + chalf]; AXPY4(s, w11, t); }
                }
                int c0 = chalf << 2;
                val_s[(c0 + 0) * 128 + p] = s.x * mask;
                val_s[(c0 + 1) * 128 + p] = s.y * mask;
                val_s[(c0 + 2) * 128 + p] = s.z * mask;
                val_s[(c0 + 3) * 128 + p] = s.w * mask;
                if (tid < 128) {
                    int c = tid >> 4, o4 = tid & 15;
                    ((float4*)w_s)[c * 16 + o4] =
                        ((const float4*)g_wdt)[((g * 8 + c) * 9 + k) * 16 + o4];
                }
                __syncthreads();
                const float4* vs4 = (const float4*)val_s;
                const float4* ws4 = (const float4*)w_s;
#pragma unroll
                for (int c = 0; c < 8; c++) {
                    int vb4 = (c * 128 + rG * 32 + xqG) >> 2;
                    float4 a0 = vs4[vb4], a1 = vs4[vb4 + 1];
                    float rr[8] = {a0.x, a0.y, a0.z, a0.w, a1.x, a1.y, a1.z, a1.w};
                    float4 wv = ws4[c * 16 + tx];
                    ull wp01 = pk2(wv.x, wv.y), wp23 = pk2(wv.z, wv.w);
#pragma unroll
                    for (int j = 0; j < 8; j++) {
                        ull v2 = pk2(rr[j], rr[j]);
                        fma2(acc0[j], wp01, v2);
                        fma2(acc1[j], wp23, v2);
                    }
                }
                __syncthreads();
            }
        }
    }

    float va[4][8];
#pragma unroll
    for (int j = 0; j < 8; j++) {
        float2 u0 = upk(acc0[j]), u1 = upk(acc1[j]);
        va[0][j] = (u0.x >= 0.f) ? u0.x : 0.2f * u0.x;
        va[1][j] = (u0.y >= 0.f) ? u0.y : 0.2f * u0.y;
        va[2][j] = (u1.x >= 0.f) ? u1.x : 0.2f * u1.x;
        va[3][j] = (u1.y >= 0.f) ? u1.y : 0.2f * u1.y;
    }
    int y = y0 + rG, xb = x0 + xqG;
#pragma unroll
    for (int q = 0; q < 4; q++) {
        int oc = oc0 + q;
        float4* dst = (float4*)(g_fea + ((size_t)b * CC + oc) * HW + y * 96 + xb);
        dst[0] = make_float4(va[q][0], va[q][1], va[q][2], va[q][3]);
        dst[1] = make_float4(va[q][4], va[q][5], va[q][6], va[q][7]);
    }
}

// ---------------- launch ----------------
extern "C" void kernel_launch(void* const* d_in, const int* in_sizes, int n_in,
                              void* d_out, int out_size) {
    const float* x       = (const float*)d_in[0];
    const float* offset  = (const float*)d_in[1];
    const float* w_off   = (const float*)d_in[2];
    const float* b_off   = (const float*)d_in[3];
    const float* w_dcn   = (const float*)d_in[4];
    const float* b_dcn   = (const float*)d_in[5];
    const float* w_conv1 = (const float*)d_in[6];
    const float* b_conv1 = (const float*)d_in[7];
    float* out = (float*)d_out;
    (void)in_sizes; (void)n_in; (void)out_size;

    k_wt<<<486, 256>>>(w_off, 0, OFFC);     // -> g_wofft
    k_wt<<<144, 256>>>(w_dcn, 1, 64);       // -> g_wdt
    k_wt<<<144, 256>>>(w_conv1, 2, 64);     // -> g_wct
    k_xt<<<3072, 96>>>(x);                  // -> g_xt

    k_conv<true><<<dim3(3, 12, 16), 256>>>(offset, b_off, nullptr);  // -> g_om
    k_dcn<<<dim3(3, 24, 4), 256>>>(b_dcn);                           // -> g_fea
    k_conv<false><<<dim3(3, 12, 4), 256>>>(x, b_conv1, out);         // -> out
}